// round 5
// baseline (speedup 1.0000x reference)
#include <cuda_runtime.h>
#include <cuda_bf16.h>
#include <math.h>
#include <stdint.h>

// Problem constants
#define BSZ   2
#define SEQ   1024
#define DMODEL 4096
#define NH    32
#define NKVH  8
#define HD    128
#define MROWS (BSZ * SEQ)      // 2048
#define QCOLS (NH * HD)        // 4096
#define KCOLS (NKVH * HD)      // 1024

// Scratch (no allocations allowed — device globals)
__device__ float g_Q [(size_t)MROWS * QCOLS];
__device__ float g_K [(size_t)MROWS * KCOLS];
__device__ float g_V [(size_t)MROWS * KCOLS];
__device__ float g_AO[(size_t)MROWS * QCOLS];

// ---------------------------------------------------------------------------
// f32x2 helpers (Blackwell packed fp32 pipe)
// ---------------------------------------------------------------------------
__device__ __forceinline__ void fma2(unsigned long long& d,
                                     unsigned long long a, unsigned long long b) {
    asm("fma.rn.f32x2 %0, %1, %2, %0;" : "+l"(d) : "l"(a), "l"(b));
}
__device__ __forceinline__ unsigned long long dup2(float x) {
    unsigned long long r;
    asm("mov.b64 %0, {%1, %1};" : "=l"(r) : "f"(x));
    return r;
}
__device__ __forceinline__ float2 unp2(unsigned long long v) {
    float lo, hi;
    asm("mov.b64 {%0, %1}, %2;" : "=f"(lo), "=f"(hi) : "l"(v));
    return make_float2(lo, hi);
}

// ---------------------------------------------------------------------------
// fp32 SGEMM on the f32x2 pipe:  C[M,N] = A[M,K] @ W[K,N] (+ bias[N])
// BM=BN=128, BK=16, 256 threads, 8x8 microtile as 8x(4 pairs).
// Double-buffered smem, register-staged prefetch, one sync per iter.
// M,N % 128 == 0, K % 16 == 0 (true for all calls).
// ---------------------------------------------------------------------------
__global__ __launch_bounds__(256)
void sgemm_f32x2(const float* __restrict__ A, const float* __restrict__ W,
                 const float* __restrict__ bias, float* __restrict__ C,
                 int M, int N, int K)
{
    __shared__ float As[2][16][128];   // As[buf][k][m] (transposed)
    __shared__ float Bs[2][16][128];   // Bs[buf][k][n]

    const int t   = threadIdx.x;
    const int tx  = t & 15;            // 16 col groups
    const int ty  = t >> 4;            // 16 row groups
    const int row0 = blockIdx.y * 128;
    const int col0 = blockIdx.x * 128;

    unsigned long long acc2[8][4];
#pragma unroll
    for (int i = 0; i < 8; i++)
#pragma unroll
        for (int j = 0; j < 4; j++) acc2[i][j] = 0ull;

    float4 pa[2], pb[2];

    auto LOAD = [&](int kb) {
#pragma unroll
        for (int q = 0; q < 2; q++) {
            int f = t + q * 256;                 // 0..511
            pa[q] = *reinterpret_cast<const float4*>(
                A + (size_t)(row0 + (f >> 2)) * K + kb + (f & 3) * 4);
            pb[q] = *reinterpret_cast<const float4*>(
                W + (size_t)(kb + (f >> 5)) * N + col0 + (f & 31) * 4);
        }
    };
    auto STORE = [&](int buf) {
#pragma unroll
        for (int q = 0; q < 2; q++) {
            int f  = t + q * 256;
            int r  = f >> 2, k4 = f & 3;
            As[buf][k4 * 4 + 0][r] = pa[q].x;
            As[buf][k4 * 4 + 1][r] = pa[q].y;
            As[buf][k4 * 4 + 2][r] = pa[q].z;
            As[buf][k4 * 4 + 3][r] = pa[q].w;
            int kk = f >> 5, n4 = f & 31;
            *reinterpret_cast<float4*>(&Bs[buf][kk][n4 * 4]) = pb[q];
        }
    };

    LOAD(0);
    STORE(0);
    __syncthreads();

    const int niter = K >> 4;
    for (int it = 0; it < niter; it++) {
        const int cur = it & 1;
        if (it + 1 < niter) LOAD((it + 1) << 4);

#pragma unroll
        for (int kk = 0; kk < 16; kk++) {
            float ra[8];
            float4 b0, b1;
            *reinterpret_cast<float4*>(&ra[0]) =
                *reinterpret_cast<const float4*>(&As[cur][kk][ty * 4]);
            *reinterpret_cast<float4*>(&ra[4]) =
                *reinterpret_cast<const float4*>(&As[cur][kk][64 + ty * 4]);
            b0 = *reinterpret_cast<const float4*>(&Bs[cur][kk][tx * 4]);
            b1 = *reinterpret_cast<const float4*>(&Bs[cur][kk][64 + tx * 4]);

            unsigned long long rb2[4];
            asm("mov.b64 %0, {%1, %2};" : "=l"(rb2[0]) : "f"(b0.x), "f"(b0.y));
            asm("mov.b64 %0, {%1, %2};" : "=l"(rb2[1]) : "f"(b0.z), "f"(b0.w));
            asm("mov.b64 %0, {%1, %2};" : "=l"(rb2[2]) : "f"(b1.x), "f"(b1.y));
            asm("mov.b64 %0, {%1, %2};" : "=l"(rb2[3]) : "f"(b1.z), "f"(b1.w));

#pragma unroll
            for (int i = 0; i < 8; i++) {
                unsigned long long ad = dup2(ra[i]);
                fma2(acc2[i][0], ad, rb2[0]);
                fma2(acc2[i][1], ad, rb2[1]);
                fma2(acc2[i][2], ad, rb2[2]);
                fma2(acc2[i][3], ad, rb2[3]);
            }
        }

        if (it + 1 < niter) {
            STORE(cur ^ 1);
            __syncthreads();
        }
    }

    // Epilogue
#pragma unroll
    for (int i = 0; i < 8; i++) {
        int r = row0 + ((i < 4) ? (ty * 4 + i) : (64 + ty * 4 + (i - 4)));
#pragma unroll
        for (int jh = 0; jh < 2; jh++) {
            int cb = col0 + (jh ? (64 + tx * 4) : (tx * 4));
            float2 p0 = unp2(acc2[i][jh * 2 + 0]);
            float2 p1 = unp2(acc2[i][jh * 2 + 1]);
            float4 v = make_float4(p0.x, p0.y, p1.x, p1.y);
            if (bias) {
                v.x += bias[cb + 0];
                v.y += bias[cb + 1];
                v.z += bias[cb + 2];
                v.w += bias[cb + 3];
            }
            *reinterpret_cast<float4*>(C + (size_t)r * N + cb) = v;
        }
    }
}

// ---------------------------------------------------------------------------
// RoPE (in-place): buf layout [MROWS][nheads*128].
// ---------------------------------------------------------------------------
__global__ void rope_kernel(float* __restrict__ buf,
                            const int* __restrict__ sidx, int nheads)
{
    int idx = blockIdx.x * blockDim.x + threadIdx.x;
    int total = MROWS * nheads * 64;
    if (idx >= total) return;
    int d   = idx & 63;
    int rem = idx >> 6;
    int h   = rem % nheads;
    int row = rem / nheads;
    int s   = row & (SEQ - 1);

    double pos = (double)sidx[s];
    double ang = pos * exp(-((double)d / 64.0) * 13.815510557964274);
    double sn, cs;
    sincos(ang, &sn, &cs);

    float* p = buf + (size_t)row * (nheads * 128) + h * 128 + d;
    float t1 = p[0];
    float t2 = p[64];
    p[0]  = t1 * (float)cs - t2 * (float)sn;
    p[64] = t2 * (float)cs + t1 * (float)sn;
}

// ---------------------------------------------------------------------------
// Flash attention (fp32, causal). BQ=64, BK=32, 256 threads.
// ---------------------------------------------------------------------------
__global__ __launch_bounds__(256)
void attn_kernel(const float* __restrict__ Q, const float* __restrict__ Kc,
                 const float* __restrict__ Vc, const int* __restrict__ sidx,
                 float* __restrict__ O)
{
    __shared__ float4 Ks[32][32];
    __shared__ float4 Vs[32][32];
    __shared__ int    spos[32];

    const int t   = threadIdx.x;
    const int r   = t >> 2;
    const int sub = t & 3;
    const int b   = blockIdx.z;
    const int h   = blockIdx.y;
    const int q0  = blockIdx.x * 64;
    const int kvh = h >> 2;
    const int sq  = q0 + r;
    const int pos_q = sidx[sq];
    const float scale = 0.08838834764831845f;

    float4 qreg[8];
    {
        const float4* qp = reinterpret_cast<const float4*>(
            Q + (size_t)(b * SEQ + sq) * QCOLS + h * 128 + sub * 32);
#pragma unroll
        for (int c = 0; c < 8; c++) qreg[c] = qp[c];
    }

    float  m = -1e30f, l = 0.f;
    float4 acc[8];
#pragma unroll
    for (int c = 0; c < 8; c++) acc[c] = make_float4(0.f, 0.f, 0.f, 0.f);

    const float* Kbase = Kc + (size_t)b * SEQ * KCOLS + kvh * 128;
    const float* Vbase = Vc + (size_t)b * SEQ * KCOLS + kvh * 128;

    for (int k0 = 0; k0 < q0 + 64; k0 += 32) {
        __syncthreads();
#pragma unroll
        for (int w = 0; w < 4; w++) {
            int f  = w * 256 + t;
            int j  = f >> 5;
            int i4 = f & 31;
            Ks[j][i4] = *reinterpret_cast<const float4*>(
                Kbase + (size_t)(k0 + j) * KCOLS + i4 * 4);
            Vs[j][i4] = *reinterpret_cast<const float4*>(
                Vbase + (size_t)(k0 + j) * KCOLS + i4 * 4);
        }
        if (t < 32) spos[t] = sidx[k0 + t];
        __syncthreads();

        float sc[32];
        float tmax = -1e30f;
#pragma unroll
        for (int j = 0; j < 32; j++) {
            float s = 0.f;
#pragma unroll
            for (int c0 = 0; c0 < 8; c0++) {
                int c = (c0 + 2 * sub) & 7;
                float4 k4 = Ks[j][sub * 8 + c];
                float4 q4 = qreg[c];
                s += q4.x * k4.x + q4.y * k4.y + q4.z * k4.z + q4.w * k4.w;
            }
            s += __shfl_xor_sync(0xffffffffu, s, 1);
            s += __shfl_xor_sync(0xffffffffu, s, 2);
            s *= scale;
            if (spos[j] > pos_q) s = -1e30f;
            sc[j] = s;
            tmax = fmaxf(tmax, s);
        }

        float m_new = fmaxf(m, tmax);
        float corr  = __expf(m - m_new);
        l *= corr;
#pragma unroll
        for (int c = 0; c < 8; c++) {
            acc[c].x *= corr; acc[c].y *= corr;
            acc[c].z *= corr; acc[c].w *= corr;
        }
#pragma unroll
        for (int j = 0; j < 32; j++) {
            float p = __expf(sc[j] - m_new);
            l += p;
#pragma unroll
            for (int c0 = 0; c0 < 8; c0++) {
                int c = (c0 + 2 * sub) & 7;
                float4 v4 = Vs[j][sub * 8 + c];
                acc[c].x += p * v4.x; acc[c].y += p * v4.y;
                acc[c].z += p * v4.z; acc[c].w += p * v4.w;
            }
        }
        m = m_new;
    }

    float inv = 1.0f / l;
    float4* op = reinterpret_cast<float4*>(
        O + (size_t)(b * SEQ + sq) * QCOLS + h * 128 + sub * 32);
#pragma unroll
    for (int c = 0; c < 8; c++) {
        float4 v = acc[c];
        v.x *= inv; v.y *= inv; v.z *= inv; v.w *= inv;
        op[c] = v;
    }
}

// ---------------------------------------------------------------------------
// Launch: QKV proj -> RoPE -> flash attention -> output proj
// ---------------------------------------------------------------------------
extern "C" void kernel_launch(void* const* d_in, const int* in_sizes, int n_in,
                              void* d_out, int out_size)
{
    (void)in_sizes; (void)n_in; (void)out_size;
    const float* x    = (const float*)d_in[0];
    const int*   sidx = (const int*)  d_in[1];
    const float* Wq = (const float*)d_in[4];
    const float* bq = (const float*)d_in[5];
    const float* Wk = (const float*)d_in[6];
    const float* bk = (const float*)d_in[7];
    const float* Wv = (const float*)d_in[8];
    const float* bv = (const float*)d_in[9];
    const float* Wo = (const float*)d_in[10];
    float* out = (float*)d_out;

    float *pQ, *pK, *pV, *pAO;
    cudaGetSymbolAddress((void**)&pQ,  g_Q);
    cudaGetSymbolAddress((void**)&pK,  g_K);
    cudaGetSymbolAddress((void**)&pV,  g_V);
    cudaGetSymbolAddress((void**)&pAO, g_AO);

    // QKV projections (+bias)
    sgemm_f32x2<<<dim3(QCOLS / 128, MROWS / 128), 256>>>(x, Wq, bq, pQ, MROWS, QCOLS, DMODEL);
    sgemm_f32x2<<<dim3(KCOLS / 128, MROWS / 128), 256>>>(x, Wk, bk, pK, MROWS, KCOLS, DMODEL);
    sgemm_f32x2<<<dim3(KCOLS / 128, MROWS / 128), 256>>>(x, Wv, bv, pV, MROWS, KCOLS, DMODEL);

    // RoPE on Q and K
    rope_kernel<<<(MROWS * NH   * 64 + 255) / 256, 256>>>(pQ, sidx, NH);
    rope_kernel<<<(MROWS * NKVH * 64 + 255) / 256, 256>>>(pK, sidx, NKVH);

    // Causal GQA flash attention
    attn_kernel<<<dim3(SEQ / 64, NH, BSZ), 256>>>(pQ, pK, pV, sidx, pAO);

    // Output projection
    sgemm_f32x2<<<dim3(DMODEL / 128, MROWS / 128), 256>>>(pAO, Wo, nullptr, out, MROWS, DMODEL, QCOLS);
}